// round 6
// baseline (speedup 1.0000x reference)
#include <cuda_runtime.h>
#include <cuda_bf16.h>

#define KDIM 4096
#define RDIM 64
#define KC 128                 // k per chunk
#define NCHUNK (KDIM / KC)     // 32
#define ASTRIDE 36             // A-smem row stride in floats (32 + 4 pad)

// out[c,r] = sum_k x[xids[c*64+r], k] * A[wids[c], k, r]
//
// Block = (c, r-half). 256 threads = 8 warps.
//   warp q (=tid>>5) owns r-quad r0 = rh*32 + 4q (4 tokens);
//   lane s (=tid&31) owns k-offsets {s, s+32, s+64, s+96} within each 128-k chunk.
// x loads coalesced (1 line per warp instr); A staged via double-buffered smem,
// ONE __syncthreads per chunk:
//   iter ch: LDG ch+1 -> regs; sync; compute buf[p]; STS regs -> buf[1-p].
// STS(buf[1-p]) vs readers of buf[1-p] (iter ch-1) separated by this iter's sync;
// readers of buf[p] see last iter's STS via the same sync.
__global__ void __launch_bounds__(256, 5) lora_gather_dot_kernel(
    const float* __restrict__ x,
    const int*   __restrict__ xids,
    const int*   __restrict__ wids,
    const float* __restrict__ A,
    float*       __restrict__ out)
{
    __shared__ float as[2][KC * ASTRIDE];   // 2 x 18432 B

    const int c   = blockIdx.x;
    const int rh  = blockIdx.y;          // r-half 0/1
    const int tid = threadIdx.x;
    const int q   = tid >> 5;            // warp id -> r-quad
    const int s   = tid & 31;            // lane -> k sub-index
    const int f   = tid & 7;             // A-load: r-quad column
    const int kk  = tid >> 3;            // A-load: k row 0..31

    const int wid   = wids[c];
    const int rbase = rh * 32;
    const int r0    = rbase + 4 * q;

    // This warp's 4 tokens (32-bit offsets: max 512*4096 < 2^31)
    const int off0 = xids[c * RDIM + r0 + 0] * KDIM;
    const int off1 = xids[c * RDIM + r0 + 1] * KDIM;
    const int off2 = xids[c * RDIM + r0 + 2] * KDIM;
    const int off3 = xids[c * RDIM + r0 + 3] * KDIM;

    // A[w][k][r]; this block's r-window starts at rbase
    const float* __restrict__ Ab = A + (size_t)wid * KDIM * RDIM + rbase;

    // ---- prologue: chunk 0 -> buf 0 ----
    float4 an0, an1, an2, an3;
    {
        const float* Ac = Ab + (size_t)kk * RDIM + 4 * f;
        an0 = *reinterpret_cast<const float4*>(Ac + 0 * 32 * RDIM);
        an1 = *reinterpret_cast<const float4*>(Ac + 1 * 32 * RDIM);
        an2 = *reinterpret_cast<const float4*>(Ac + 2 * 32 * RDIM);
        an3 = *reinterpret_cast<const float4*>(Ac + 3 * 32 * RDIM);
    }
    *reinterpret_cast<float4*>(&as[0][(kk +  0) * ASTRIDE + 4 * f]) = an0;
    *reinterpret_cast<float4*>(&as[0][(kk + 32) * ASTRIDE + 4 * f]) = an1;
    *reinterpret_cast<float4*>(&as[0][(kk + 64) * ASTRIDE + 4 * f]) = an2;
    *reinterpret_cast<float4*>(&as[0][(kk + 96) * ASTRIDE + 4 * f]) = an3;

    float acc0 = 0.f, acc1 = 0.f, acc2 = 0.f, acc3 = 0.f;
    int p = 0;

    for (int ch = 0; ch < NCHUNK; ++ch) {
        const int kc = ch * KC;

        // issue next chunk's gmem loads first (latency overlaps compute below)
        if (ch + 1 < NCHUNK) {
            const float* Ac = Ab + (size_t)(kc + KC + kk) * RDIM + 4 * f;
            an0 = *reinterpret_cast<const float4*>(Ac + 0 * 32 * RDIM);
            an1 = *reinterpret_cast<const float4*>(Ac + 1 * 32 * RDIM);
            an2 = *reinterpret_cast<const float4*>(Ac + 2 * 32 * RDIM);
            an3 = *reinterpret_cast<const float4*>(Ac + 3 * 32 * RDIM);
        }

        __syncthreads();   // buf[p] stores visible; buf[1-p] readers (prev iter) done

        // compute this chunk from buf[p]: 4 k-groups of 32
        #pragma unroll
        for (int i = 0; i < 4; ++i) {
            const int kl = s + 32 * i;
            const float4 av =
                *reinterpret_cast<const float4*>(&as[p][kl * ASTRIDE + 4 * q]);
            const int kx = kc + kl;
            acc0 += x[off0 + kx] * av.x;
            acc1 += x[off1 + kx] * av.y;
            acc2 += x[off2 + kx] * av.z;
            acc3 += x[off3 + kx] * av.w;
        }

        // stage next chunk into the other buffer
        if (ch + 1 < NCHUNK) {
            const int np = p ^ 1;
            *reinterpret_cast<float4*>(&as[np][(kk +  0) * ASTRIDE + 4 * f]) = an0;
            *reinterpret_cast<float4*>(&as[np][(kk + 32) * ASTRIDE + 4 * f]) = an1;
            *reinterpret_cast<float4*>(&as[np][(kk + 64) * ASTRIDE + 4 * f]) = an2;
            *reinterpret_cast<float4*>(&as[np][(kk + 96) * ASTRIDE + 4 * f]) = an3;
            p = np;
        }
    }

    // reduce over the 32 lanes (k) within each warp
    #pragma unroll
    for (int off = 16; off > 0; off >>= 1) {
        acc0 += __shfl_xor_sync(0xffffffffu, acc0, off);
        acc1 += __shfl_xor_sync(0xffffffffu, acc1, off);
        acc2 += __shfl_xor_sync(0xffffffffu, acc2, off);
        acc3 += __shfl_xor_sync(0xffffffffu, acc3, off);
    }
    if (s == 0) {
        float4 o = make_float4(acc0, acc1, acc2, acc3);
        *reinterpret_cast<float4*>(&out[c * RDIM + r0]) = o;
    }
}

extern "C" void kernel_launch(void* const* d_in, const int* in_sizes, int n_in,
                              void* d_out, int out_size)
{
    const float* x    = (const float*)d_in[0];   // [512,1,4096] f32
    const int*   xids = (const int*)  d_in[1];   // [20480] i32
    const int*   wids = (const int*)  d_in[2];   // [320] i32
    const float* A    = (const float*)d_in[3];   // [80,4096,64] f32
    float*       out  = (float*)d_out;           // [320,1,64] f32

    const int C = in_sizes[2];                   // COMBINED_BS (320)
    dim3 grid(C, 2);                             // (c, r-half)
    lora_gather_dot_kernel<<<grid, 256>>>(x, xids, wids, A, out);
}

// round 7
// speedup vs baseline: 1.1420x; 1.1420x over previous
#include <cuda_runtime.h>
#include <cuda_bf16.h>
#include <cstdint>

#define KDIM 4096
#define RDIM 64
#define KC 128                  // k per chunk
#define NCHUNK (KDIM / KC)      // 32
#define ASTRIDE 36              // A-smem row stride in floats (32 + 4 pad) = 144 B
#define CHUNK_TX (KC * 128)     // bytes delivered per chunk: 128 rows x 128 B

// out[c,r] = sum_k x[xids[c*64+r], k] * A[wids[c], k, r]
//
// Block = (c, r-half). 256 threads = 8 warps.
//   warp q owns r-quad r0 = rh*32 + 4q (4 tokens); lane s owns k = {s,s+32,s+64,s+96}.
// x: direct LDG, fully coalesced (1 line / warp instr).
// A: staged per 128-k chunk via cp.async.bulk (TMA path, bypasses L1tex wavefronts)
//    into double-buffered smem with the padded conflict-free layout.
//    Per chunk: 128 row copies of 128 B (gmem stride 256 B -> per-row bulk copies),
//    mbarrier expect_tx = 16 KB. End-of-iter __syncthreads = buffer-empty condition.
__global__ void __launch_bounds__(256, 5) lora_gather_dot_kernel(
    const float* __restrict__ x,
    const int*   __restrict__ xids,
    const int*   __restrict__ wids,
    const float* __restrict__ A,
    float*       __restrict__ out)
{
    __shared__ __align__(128) float as[2][KC * ASTRIDE];   // 2 x 18432 B
    __shared__ __align__(8) unsigned long long mbar[2];

    const int c   = blockIdx.x;
    const int rh  = blockIdx.y;          // r-half 0/1
    const int tid = threadIdx.x;
    const int q   = tid >> 5;            // warp id -> r-quad
    const int s   = tid & 31;            // lane -> k sub-index

    const int wid   = wids[c];
    const int rbase = rh * 32;
    const int r0    = rbase + 4 * q;

    const int off0 = xids[c * RDIM + r0 + 0] * KDIM;
    const int off1 = xids[c * RDIM + r0 + 1] * KDIM;
    const int off2 = xids[c * RDIM + r0 + 2] * KDIM;
    const int off3 = xids[c * RDIM + r0 + 3] * KDIM;

    // A[w][k][r]; this block's 32-r window starts at rbase (gmem rows: 128 B @ stride 256 B)
    const float* __restrict__ Ab = A + (size_t)wid * KDIM * RDIM + rbase;

    // smem u32 addresses
    uint32_t as_u32[2], mb_u32[2];
    {
        uint32_t a0;
        asm("{ .reg .u64 t; cvta.to.shared.u64 t, %1; cvt.u32.u64 %0, t; }"
            : "=r"(a0) : "l"(&as[0][0]));
        as_u32[0] = a0;
        asm("{ .reg .u64 t; cvta.to.shared.u64 t, %1; cvt.u32.u64 %0, t; }"
            : "=r"(a0) : "l"(&as[1][0]));
        as_u32[1] = a0;
        asm("{ .reg .u64 t; cvta.to.shared.u64 t, %1; cvt.u32.u64 %0, t; }"
            : "=r"(a0) : "l"(&mbar[0]));
        mb_u32[0] = a0;
        mb_u32[1] = a0 + 8;
    }

    if (tid == 0) {
        asm volatile("mbarrier.init.shared::cta.b64 [%0], 1;" :: "r"(mb_u32[0]) : "memory");
        asm volatile("mbarrier.init.shared::cta.b64 [%0], 1;" :: "r"(mb_u32[1]) : "memory");
    }
    __syncthreads();

    // ---- prologue: issue chunk 0 -> buf 0 ----
    if (tid == 0) {
        asm volatile("mbarrier.arrive.expect_tx.shared::cta.b64 _, [%0], %1;"
                     :: "r"(mb_u32[0]), "r"((uint32_t)CHUNK_TX) : "memory");
    }
    if (tid < KC) {
        const float* src = Ab + (size_t)tid * RDIM;
        uint32_t dst = as_u32[0] + tid * (ASTRIDE * 4);
        asm volatile(
            "cp.async.bulk.shared::cluster.global.mbarrier::complete_tx::bytes "
            "[%0], [%1], %2, [%3];"
            :: "r"(dst), "l"(src), "r"(128u), "r"(mb_u32[0]) : "memory");
    }

    float acc0 = 0.f, acc1 = 0.f, acc2 = 0.f, acc3 = 0.f;
    int ph0 = 0, ph1 = 0;

    for (int ch = 0; ch < NCHUNK; ++ch) {
        const int b  = ch & 1;
        const int kc = ch * KC;

        // issue next chunk into the other buffer (its readers finished before
        // the __syncthreads that ended iter ch-1)
        if (ch + 1 < NCHUNK) {
            const int nb = b ^ 1;
            if (tid == 0) {
                asm volatile("mbarrier.arrive.expect_tx.shared::cta.b64 _, [%0], %1;"
                             :: "r"(mb_u32[nb]), "r"((uint32_t)CHUNK_TX) : "memory");
            }
            if (tid < KC) {
                const float* src = Ab + (size_t)(kc + KC + tid) * RDIM;
                uint32_t dst = as_u32[nb] + tid * (ASTRIDE * 4);
                asm volatile(
                    "cp.async.bulk.shared::cluster.global.mbarrier::complete_tx::bytes "
                    "[%0], [%1], %2, [%3];"
                    :: "r"(dst), "l"(src), "r"(128u), "r"(mb_u32[b ^ 1]) : "memory");
            }
        }

        // wait for this chunk's data (acquire orders subsequent LDS)
        {
            const uint32_t mb = mb_u32[b];
            const uint32_t ph = (uint32_t)(b ? ph1 : ph0);
            uint32_t done;
            do {
                asm volatile(
                    "{ .reg .pred p; "
                    "mbarrier.try_wait.parity.acquire.cta.shared::cta.b64 p, [%1], %2, 0x989680; "
                    "selp.b32 %0, 1, 0, p; }"
                    : "=r"(done) : "r"(mb), "r"(ph) : "memory");
            } while (!done);
            if (b) ph1 ^= 1; else ph0 ^= 1;
        }

        // compute this chunk from buf[b]: 4 k-groups of 32
        const float* asb = &as[b][0];
        #pragma unroll
        for (int i = 0; i < 4; ++i) {
            const int kl = s + 32 * i;
            const float4 av =
                *reinterpret_cast<const float4*>(&asb[kl * ASTRIDE + 4 * q]);
            const int kx = kc + kl;
            acc0 += x[off0 + kx] * av.x;
            acc1 += x[off1 + kx] * av.y;
            acc2 += x[off2 + kx] * av.z;
            acc3 += x[off3 + kx] * av.w;
        }

        if (ch + 1 < NCHUNK) __syncthreads();   // readers of buf[b] done -> safe to refill
    }

    // reduce over the 32 lanes (k) within each warp
    #pragma unroll
    for (int off = 16; off > 0; off >>= 1) {
        acc0 += __shfl_xor_sync(0xffffffffu, acc0, off);
        acc1 += __shfl_xor_sync(0xffffffffu, acc1, off);
        acc2 += __shfl_xor_sync(0xffffffffu, acc2, off);
        acc3 += __shfl_xor_sync(0xffffffffu, acc3, off);
    }
    if (s == 0) {
        float4 o = make_float4(acc0, acc1, acc2, acc3);
        *reinterpret_cast<float4*>(&out[c * RDIM + r0]) = o;
    }
}

extern "C" void kernel_launch(void* const* d_in, const int* in_sizes, int n_in,
                              void* d_out, int out_size)
{
    const float* x    = (const float*)d_in[0];   // [512,1,4096] f32
    const int*   xids = (const int*)  d_in[1];   // [20480] i32
    const int*   wids = (const int*)  d_in[2];   // [320] i32
    const float* A    = (const float*)d_in[3];   // [80,4096,64] f32
    float*       out  = (float*)d_out;           // [320,1,64] f32

    const int C = in_sizes[2];                   // COMBINED_BS (320)
    dim3 grid(C, 2);                             // (c, r-half)
    lora_gather_dot_kernel<<<grid, 256>>>(x, xids, wids, A, out);
}